// round 1
// baseline (speedup 1.0000x reference)
#include <cuda_runtime.h>
#include <cuda_bf16.h>

#define NHEADS 20
#define HEAD_DIM 64
#define HIDDEN 1280
#define CROSS 2048
#define NB 4
#define SQ 4096
#define TXT 77
#define NTOK 4
#define ENC (TXT + NTOK)

// Scratch (static device allocations; allowed)
__device__ float g_q[NB * SQ * HIDDEN];
__device__ float g_hs[NB * SQ * HIDDEN];
__device__ float g_k[NB * TXT * HIDDEN];
__device__ float g_v[NB * TXT * HIDDEN];
__device__ float g_ipk[NB * NTOK * HIDDEN];
__device__ float g_ipv[NB * NTOK * HIDDEN];

// ---------------------------------------------------------------------------
// Tiled SGEMM: C[M,N] = A[M,K] @ B[K,N]  (+ optional bias + residual)
// BM=BN=64, BK=16, 256 threads, 4x4 microtile.
// Requirements: N % 64 == 0, K % 16 == 0. M arbitrary (row-guarded).
// blockIdx.z batches A and C by strides sA/sC.
// ---------------------------------------------------------------------------
__global__ __launch_bounds__(256)
void sgemm_kernel(const float* __restrict__ A, const float* __restrict__ Bm,
                  float* __restrict__ C, int M, int N, int K,
                  long sA, long sC,
                  const float* __restrict__ bias,
                  const float* __restrict__ resid)
{
    const int BM = 64, BN = 64, BK = 16;
    __shared__ float As[BK][BM];
    __shared__ float Bs[BK][BN];

    A += blockIdx.z * sA;
    C += blockIdx.z * sC;

    int tid  = threadIdx.x;
    int brow = blockIdx.y * BM;
    int bcol = blockIdx.x * BN;

    // load-phase indices
    int arow  = tid >> 2;         // 0..63
    int acol  = (tid & 3) * 4;    // 0,4,8,12
    int bkrow = tid >> 4;         // 0..15
    int bcol4 = (tid & 15) * 4;   // 0..60

    // compute-phase indices
    int ty = tid >> 4;            // 0..15
    int tx = tid & 15;            // 0..15

    float acc[4][4] = {};

    for (int k0 = 0; k0 < K; k0 += BK) {
        // A tile (row-guarded)
        {
            int gr = brow + arow;
            float4 a = make_float4(0.f, 0.f, 0.f, 0.f);
            if (gr < M) a = *(const float4*)(A + (long)gr * K + k0 + acol);
            As[acol + 0][arow] = a.x;
            As[acol + 1][arow] = a.y;
            As[acol + 2][arow] = a.z;
            As[acol + 3][arow] = a.w;
        }
        // B tile (always in-bounds: K%16==0, N%64==0)
        {
            float4 b = *(const float4*)(Bm + (long)(k0 + bkrow) * N + bcol + bcol4);
            *(float4*)&Bs[bkrow][bcol4] = b;
        }
        __syncthreads();

        #pragma unroll
        for (int kk = 0; kk < BK; kk++) {
            float4 am = *(float4*)&As[kk][ty * 4];
            float4 bn = *(float4*)&Bs[kk][tx * 4];
            float rm[4] = {am.x, am.y, am.z, am.w};
            float rn[4] = {bn.x, bn.y, bn.z, bn.w};
            #pragma unroll
            for (int i = 0; i < 4; i++)
                #pragma unroll
                for (int j = 0; j < 4; j++)
                    acc[i][j] = fmaf(rm[i], rn[j], acc[i][j]);
        }
        __syncthreads();
    }

    // epilogue
    #pragma unroll
    for (int i = 0; i < 4; i++) {
        int gr = brow + ty * 4 + i;
        if (gr >= M) break;
        int gc = bcol + tx * 4;
        float4 o = make_float4(acc[i][0], acc[i][1], acc[i][2], acc[i][3]);
        if (bias) {
            float4 bi = *(const float4*)(bias + gc);
            float4 rr = *(const float4*)(resid + (long)gr * N + gc);
            o.x += bi.x + rr.x;
            o.y += bi.y + rr.y;
            o.z += bi.z + rr.z;
            o.w += bi.w + rr.w;
        }
        *(float4*)(C + (long)gr * N + gc) = o;
    }
}

// ---------------------------------------------------------------------------
// Attention: per-thread q-row, K/V (77 text keys + 4 ip keys) in smem.
// Text softmax always; ip softmax added (IP_SCALE=1) only for odd batches
// (batches 0 and 2 are reset to raw_hs in the reference).
// grid: (SQ/128, NHEADS, NB), block: 128 threads.
// ---------------------------------------------------------------------------
__global__ __launch_bounds__(128)
void attn_kernel(const float* __restrict__ q, const float* __restrict__ k,
                 const float* __restrict__ v, const float* __restrict__ ipk,
                 const float* __restrict__ ipv, float* __restrict__ hs)
{
    __shared__ float ks[TXT][HEAD_DIM];
    __shared__ float vs[TXT][HEAD_DIM];
    __shared__ float ipks[NTOK][HEAD_DIM];
    __shared__ float ipvs[NTOK][HEAD_DIM];

    const int b   = blockIdx.z;
    const int h   = blockIdx.y;
    const int row = blockIdx.x * blockDim.x + threadIdx.x;

    // stage K/V tiles for this (b, h)
    for (int i = threadIdx.x; i < TXT * (HEAD_DIM / 4); i += blockDim.x) {
        int r = i >> 4, c4 = (i & 15) * 4;
        long off = ((long)b * TXT + r) * HIDDEN + h * HEAD_DIM + c4;
        *(float4*)&ks[r][c4] = *(const float4*)(k + off);
        *(float4*)&vs[r][c4] = *(const float4*)(v + off);
    }
    for (int i = threadIdx.x; i < NTOK * (HEAD_DIM / 4); i += blockDim.x) {
        int r = i >> 4, c4 = (i & 15) * 4;
        long off = ((long)b * NTOK + r) * HIDDEN + h * HEAD_DIM + c4;
        *(float4*)&ipks[r][c4] = *(const float4*)(ipk + off);
        *(float4*)&ipvs[r][c4] = *(const float4*)(ipv + off);
    }
    __syncthreads();

    // q row -> registers
    float qr[HEAD_DIM];
    {
        const float* qp = q + ((long)b * SQ + row) * HIDDEN + h * HEAD_DIM;
        #pragma unroll
        for (int i = 0; i < 16; i++) {
            float4 t = *(const float4*)(qp + i * 4);
            qr[4 * i + 0] = t.x; qr[4 * i + 1] = t.y;
            qr[4 * i + 2] = t.z; qr[4 * i + 3] = t.w;
        }
    }

    const float scale = 0.125f;  // 1/sqrt(64)

    // pass 1: max score over text keys
    float m = -1e30f;
    for (int key = 0; key < TXT; key++) {
        const float4* kk4 = (const float4*)ks[key];
        float s = 0.f;
        #pragma unroll
        for (int i = 0; i < 16; i++) {
            float4 t = kk4[i];
            s = fmaf(qr[4*i+0], t.x, s);
            s = fmaf(qr[4*i+1], t.y, s);
            s = fmaf(qr[4*i+2], t.z, s);
            s = fmaf(qr[4*i+3], t.w, s);
        }
        m = fmaxf(m, s * scale);
    }

    // pass 2: exp-accumulate
    float acc[HEAD_DIM];
    #pragma unroll
    for (int d = 0; d < HEAD_DIM; d++) acc[d] = 0.f;
    float l = 0.f;
    for (int key = 0; key < TXT; key++) {
        const float4* kk4 = (const float4*)ks[key];
        float s = 0.f;
        #pragma unroll
        for (int i = 0; i < 16; i++) {
            float4 t = kk4[i];
            s = fmaf(qr[4*i+0], t.x, s);
            s = fmaf(qr[4*i+1], t.y, s);
            s = fmaf(qr[4*i+2], t.z, s);
            s = fmaf(qr[4*i+3], t.w, s);
        }
        float p = __expf(s * scale - m);
        l += p;
        const float4* vv4 = (const float4*)vs[key];
        #pragma unroll
        for (int i = 0; i < 16; i++) {
            float4 t = vv4[i];
            acc[4*i+0] = fmaf(p, t.x, acc[4*i+0]);
            acc[4*i+1] = fmaf(p, t.y, acc[4*i+1]);
            acc[4*i+2] = fmaf(p, t.z, acc[4*i+2]);
            acc[4*i+3] = fmaf(p, t.w, acc[4*i+3]);
        }
    }
    float inv = 1.f / l;
    #pragma unroll
    for (int d = 0; d < HEAD_DIM; d++) acc[d] *= inv;

    // ip attention (separate softmax over 4 keys), only odd batches
    if (b & 1) {
        float sm[NTOK];
        float m2 = -1e30f;
        #pragma unroll
        for (int key = 0; key < NTOK; key++) {
            const float4* kk4 = (const float4*)ipks[key];
            float s = 0.f;
            #pragma unroll
            for (int i = 0; i < 16; i++) {
                float4 t = kk4[i];
                s = fmaf(qr[4*i+0], t.x, s);
                s = fmaf(qr[4*i+1], t.y, s);
                s = fmaf(qr[4*i+2], t.z, s);
                s = fmaf(qr[4*i+3], t.w, s);
            }
            sm[key] = s * scale;
            m2 = fmaxf(m2, sm[key]);
        }
        float l2 = 0.f;
        float p[NTOK];
        #pragma unroll
        for (int key = 0; key < NTOK; key++) { p[key] = __expf(sm[key] - m2); l2 += p[key]; }
        float inv2 = 1.f / l2;
        #pragma unroll
        for (int key = 0; key < NTOK; key++) {
            float pw = p[key] * inv2;
            const float4* vv4 = (const float4*)ipvs[key];
            #pragma unroll
            for (int i = 0; i < 16; i++) {
                float4 t = vv4[i];
                acc[4*i+0] = fmaf(pw, t.x, acc[4*i+0]);
                acc[4*i+1] = fmaf(pw, t.y, acc[4*i+1]);
                acc[4*i+2] = fmaf(pw, t.z, acc[4*i+2]);
                acc[4*i+3] = fmaf(pw, t.w, acc[4*i+3]);
            }
        }
    }

    float* op = hs + ((long)b * SQ + row) * HIDDEN + h * HEAD_DIM;
    #pragma unroll
    for (int i = 0; i < 16; i++)
        *(float4*)(op + i * 4) = make_float4(acc[4*i+0], acc[4*i+1], acc[4*i+2], acc[4*i+3]);
}

// ---------------------------------------------------------------------------
// Launcher: 5 GEMMs -> attention -> out projection (+bias+residual)
// ---------------------------------------------------------------------------
extern "C" void kernel_launch(void* const* d_in, const int* in_sizes, int n_in,
                              void* d_out, int out_size)
{
    const float* hidden = (const float*)d_in[0];  // (4,4096,1280)
    const float* enc    = (const float*)d_in[1];  // (4,81,2048)
    const float* Wq     = (const float*)d_in[2];
    const float* Wk     = (const float*)d_in[3];
    const float* Wv     = (const float*)d_in[4];
    const float* Wk_ip  = (const float*)d_in[5];
    const float* Wv_ip  = (const float*)d_in[6];
    const float* Wout   = (const float*)d_in[7];
    const float* b_out  = (const float*)d_in[8];
    float* out = (float*)d_out;

    float *q, *hs, *k, *v, *ipk, *ipv;
    cudaGetSymbolAddress((void**)&q,   g_q);
    cudaGetSymbolAddress((void**)&hs,  g_hs);
    cudaGetSymbolAddress((void**)&k,   g_k);
    cudaGetSymbolAddress((void**)&v,   g_v);
    cudaGetSymbolAddress((void**)&ipk, g_ipk);
    cudaGetSymbolAddress((void**)&ipv, g_ipv);

    const int M_big = NB * SQ;  // 16384

    // Q = hidden @ Wq              (16384,1280,1280)
    sgemm_kernel<<<dim3(HIDDEN / 64, M_big / 64, 1), 256>>>(
        hidden, Wq, q, M_big, HIDDEN, HIDDEN, 0, 0, nullptr, nullptr);

    // K = text_ctx @ Wk            per-batch (77,1280,2048)
    sgemm_kernel<<<dim3(HIDDEN / 64, (TXT + 63) / 64, NB), 256>>>(
        enc, Wk, k, TXT, HIDDEN, CROSS, (long)ENC * CROSS, (long)TXT * HIDDEN,
        nullptr, nullptr);

    // V = text_ctx @ Wv
    sgemm_kernel<<<dim3(HIDDEN / 64, (TXT + 63) / 64, NB), 256>>>(
        enc, Wv, v, TXT, HIDDEN, CROSS, (long)ENC * CROSS, (long)TXT * HIDDEN,
        nullptr, nullptr);

    // ipK = ip_ctx @ Wk_ip         per-batch (4,1280,2048)
    sgemm_kernel<<<dim3(HIDDEN / 64, 1, NB), 256>>>(
        enc + (long)TXT * CROSS, Wk_ip, ipk, NTOK, HIDDEN, CROSS,
        (long)ENC * CROSS, (long)NTOK * HIDDEN, nullptr, nullptr);

    // ipV = ip_ctx @ Wv_ip
    sgemm_kernel<<<dim3(HIDDEN / 64, 1, NB), 256>>>(
        enc + (long)TXT * CROSS, Wv_ip, ipv, NTOK, HIDDEN, CROSS,
        (long)ENC * CROSS, (long)NTOK * HIDDEN, nullptr, nullptr);

    // attention -> hs
    attn_kernel<<<dim3(SQ / 128, NHEADS, NB), 128>>>(q, k, v, ipk, ipv, hs);

    // out = hs @ Wout + b_out + residual
    sgemm_kernel<<<dim3(HIDDEN / 64, M_big / 64, 1), 256>>>(
        hs, Wout, out, M_big, HIDDEN, HIDDEN, 0, 0, b_out, hidden);
}

// round 3
// speedup vs baseline: 2.6225x; 2.6225x over previous
#include <cuda_runtime.h>
#include <cuda_bf16.h>
#include <cstdint>

#define NHEADS 20
#define HEAD_DIM 64
#define HIDDEN 1280
#define CROSS 2048
#define NB 4
#define SQ 4096
#define TXT 77
#define NTOK 4
#define ENC (TXT + NTOK)

// ============================================================================
// PTX helpers (baseline-family only: mma.sync / ldmatrix / cp.async)
// ============================================================================
__device__ __forceinline__ uint32_t smem_to_u32(const void* smem_ptr) {
    uint32_t addr;
    asm("{ .reg .u64 tmp; cvta.to.shared.u64 tmp, %1; cvt.u32.u64 %0, tmp; }"
        : "=r"(addr) : "l"(smem_ptr));
    return addr;
}

__device__ __forceinline__ void cp_async16(uint32_t dst, const void* src, int bytes) {
    asm volatile("cp.async.cg.shared.global [%0], [%1], 16, %2;"
                 :: "r"(dst), "l"(src), "r"(bytes));
}
#define CP_COMMIT() asm volatile("cp.async.commit_group;" ::: "memory")
#define CP_WAIT(N)  asm volatile("cp.async.wait_group %0;" :: "n"(N) : "memory")

__device__ __forceinline__ void ldsm_x4(uint32_t* r, uint32_t a) {
    asm volatile("ldmatrix.sync.aligned.m8n8.x4.shared.b16 {%0,%1,%2,%3}, [%4];"
                 : "=r"(r[0]), "=r"(r[1]), "=r"(r[2]), "=r"(r[3]) : "r"(a));
}

__device__ __forceinline__ void mma16816(float* c, const uint32_t* a,
                                         uint32_t b0, uint32_t b1) {
    asm volatile(
        "mma.sync.aligned.m16n8k16.row.col.f32.bf16.bf16.f32 "
        "{%0,%1,%2,%3},{%4,%5,%6,%7},{%8,%9},{%0,%1,%2,%3};"
        : "+f"(c[0]), "+f"(c[1]), "+f"(c[2]), "+f"(c[3])
        : "r"(a[0]), "r"(a[1]), "r"(a[2]), "r"(a[3]), "r"(b0), "r"(b1));
}

// ============================================================================
// Scratch (static device allocations)
// ============================================================================
__device__ __nv_bfloat16 g_ahi[NB * SQ * HIDDEN];
__device__ __nv_bfloat16 g_alo[NB * SQ * HIDDEN];
__device__ __nv_bfloat16 g_ehi[NB * ENC * CROSS];
__device__ __nv_bfloat16 g_elo[NB * ENC * CROSS];
__device__ __nv_bfloat16 g_wqT_hi[HIDDEN * HIDDEN];
__device__ __nv_bfloat16 g_wqT_lo[HIDDEN * HIDDEN];
__device__ __nv_bfloat16 g_wT_hi[4 * HIDDEN * CROSS];   // wk, wv, wkip, wvip (transposed)
__device__ __nv_bfloat16 g_wT_lo[4 * HIDDEN * CROSS];
__device__ __nv_bfloat16 g_woutT_hi[HIDDEN * HIDDEN];
__device__ __nv_bfloat16 g_woutT_lo[HIDDEN * HIDDEN];
__device__ float g_q[NB * SQ * HIDDEN];
__device__ float g_hs[NB * SQ * HIDDEN];
__device__ float g_kv[4 * NB * TXT * HIDDEN];           // k, v, ipk, ipv (uniform stride)

// ============================================================================
// fp32 -> bf16 hi/lo split (float4 vectorized)
// ============================================================================
__global__ __launch_bounds__(256)
void split_kernel(const float* __restrict__ in, __nv_bfloat16* __restrict__ hi,
                  __nv_bfloat16* __restrict__ lo, int n4)
{
    int i = blockIdx.x * blockDim.x + threadIdx.x;
    if (i >= n4) return;
    float4 x = ((const float4*)in)[i];
    __nv_bfloat16 h0 = __float2bfloat16(x.x);
    __nv_bfloat16 h1 = __float2bfloat16(x.y);
    __nv_bfloat16 h2 = __float2bfloat16(x.z);
    __nv_bfloat16 h3 = __float2bfloat16(x.w);
    __nv_bfloat162 hA; hA.x = h0; hA.y = h1;
    __nv_bfloat162 hB; hB.x = h2; hB.y = h3;
    ((__nv_bfloat162*)hi)[2 * i]     = hA;
    ((__nv_bfloat162*)hi)[2 * i + 1] = hB;
    __nv_bfloat162 lA;
    lA.x = __float2bfloat16(x.x - __bfloat162float(h0));
    lA.y = __float2bfloat16(x.y - __bfloat162float(h1));
    __nv_bfloat162 lB;
    lB.x = __float2bfloat16(x.z - __bfloat162float(h2));
    lB.y = __float2bfloat16(x.w - __bfloat162float(h3));
    ((__nv_bfloat162*)lo)[2 * i]     = lA;
    ((__nv_bfloat162*)lo)[2 * i + 1] = lB;
}

// ============================================================================
// Transpose + split: in[K][N] fp32 -> out_hi/out_lo [N][K] bf16
// ============================================================================
__global__ __launch_bounds__(256)
void transpose_split_kernel(const float* __restrict__ in, int K, int N,
                            __nv_bfloat16* __restrict__ ohi,
                            __nv_bfloat16* __restrict__ olo)
{
    __shared__ float t[32][33];
    const int tx = threadIdx.x, ty = threadIdx.y;
    const int n0 = blockIdx.x * 32, k0 = blockIdx.y * 32;
    #pragma unroll
    for (int j = ty; j < 32; j += 8)
        t[j][tx] = in[(long)(k0 + j) * N + n0 + tx];
    __syncthreads();
    #pragma unroll
    for (int j = ty; j < 32; j += 8) {
        float x = t[tx][j];
        __nv_bfloat16 h = __float2bfloat16(x);
        long o = (long)(n0 + j) * K + k0 + tx;
        ohi[o] = h;
        olo[o] = __float2bfloat16(x - __bfloat162float(h));
    }
}

// ============================================================================
// HMMA GEMM: C[M,N] = (Ahi+Alo)[M,K] @ (Bhi+Blo)^T  (B stored [N][K] bf16)
// CTA tile 128x128x32, 8 warps (warp tile 32x64), cp.async double buffer.
// 3-term bf16 split. Optional fused bias+residual.
// kvmode: blockIdx.z encodes (gemm = z>>2, batch = z&3) for the merged
//         K/V/ipK/ipV projection launch.
// ============================================================================
#define LDS_ROW 80            // 32 bf16 data + 8 pad = 80 bytes (conflict-free)
#define ABUF    10240         // 128 rows * 80B, per stage per array
#define OFF_AHI 0
#define OFF_ALO 20480
#define OFF_BHI 40960
#define OFF_BLO 61440
#define SMEM_TOT 81920

struct GemmArgs {
    const __nv_bfloat16 *Ahi, *Alo, *Bhi, *Blo;
    float* C;
    long aBatch, cBatch;
    int Mvalid, K, ldc;
    const float *bias, *resid;
    int kvmode;
};

__device__ __forceinline__ void gemm_load_stage(
    uint32_t smb, int s, int tid, int rowBase, int colBase, int Mvalid, int K,
    const __nv_bfloat16* __restrict__ Ahi, const __nv_bfloat16* __restrict__ Alo,
    const __nv_bfloat16* __restrict__ Bhi, const __nv_bfloat16* __restrict__ Blo)
{
    const int b = s & 1;
    const long k0 = (long)s << 5;
    #pragma unroll
    for (int i = 0; i < 2; i++) {
        int idx = tid + i * 256;          // 0..511
        int r = idx >> 2, c = idx & 3;
        uint32_t d = smb + (uint32_t)(b * ABUF + r * LDS_ROW + c * 16);
        long go = ((long)(rowBase + r)) * K + k0 + c * 8;
        int bytes = (rowBase + r < Mvalid) ? 16 : 0;
        cp_async16(d + OFF_AHI, Ahi + go, bytes);
        cp_async16(d + OFF_ALO, Alo + go, bytes);
        long gb = ((long)(colBase + r)) * K + k0 + c * 8;
        cp_async16(d + OFF_BHI, Bhi + gb, 16);
        cp_async16(d + OFF_BLO, Blo + gb, 16);
    }
    CP_COMMIT();
}

__global__ __launch_bounds__(256)
void hmma_gemm(GemmArgs args)
{
    extern __shared__ __align__(16) char smx[];
    const uint32_t smb = smem_to_u32(smx);
    const int tid = threadIdx.x;

    const __nv_bfloat16* Ahi = args.Ahi;
    const __nv_bfloat16* Alo = args.Alo;
    const __nv_bfloat16* Bhi = args.Bhi;
    const __nv_bfloat16* Blo = args.Blo;
    float* C = args.C;
    int Mvalid = args.Mvalid;
    const int K = args.K, ldc = args.ldc;

    if (args.kvmode) {
        const int gemm = blockIdx.z >> 2;
        const int batch = blockIdx.z & 3;
        const long aoff = (long)batch * ENC * CROSS + (gemm >= 2 ? (long)TXT * CROSS : 0);
        Ahi += aoff;  Alo += aoff;
        Bhi += (long)gemm * HIDDEN * CROSS;
        Blo += (long)gemm * HIDDEN * CROSS;
        C   += ((long)gemm * NB + batch) * TXT * HIDDEN;
        Mvalid = (gemm < 2) ? TXT : NTOK;
    } else {
        Ahi += blockIdx.z * args.aBatch;
        Alo += blockIdx.z * args.aBatch;
        C   += blockIdx.z * args.cBatch;
    }

    const int rowBase = blockIdx.y * 128;
    const int colBase = blockIdx.x * 128;
    const int NS = K >> 5;

    const int warp = tid >> 5, lane = tid & 31;
    const int wm = warp >> 1, wn = warp & 1;
    const int m0 = wm * 32, n0 = wn * 64;

    // ldmatrix per-lane offsets
    const uint32_t aoffs = (uint32_t)((m0 + (lane & 15)) * LDS_ROW + (lane >> 4) * 16);
    const uint32_t boffs = (uint32_t)((n0 + ((lane >> 4) & 1) * 8 + (lane & 7)) * LDS_ROW
                                      + ((lane >> 3) & 1) * 16);

    float acc[2][8][4];
    #pragma unroll
    for (int mi = 0; mi < 2; mi++)
        #pragma unroll
        for (int nj = 0; nj < 8; nj++)
            #pragma unroll
            for (int t = 0; t < 4; t++) acc[mi][nj][t] = 0.f;

    gemm_load_stage(smb, 0, tid, rowBase, colBase, Mvalid, K, Ahi, Alo, Bhi, Blo);

    for (int s = 0; s < NS; ++s) {
        if (s + 1 < NS) {
            gemm_load_stage(smb, s + 1, tid, rowBase, colBase, Mvalid, K, Ahi, Alo, Bhi, Blo);
            CP_WAIT(1);
        } else {
            CP_WAIT(0);
        }
        __syncthreads();

        const int b = s & 1;
        const uint32_t aHi = smb + OFF_AHI + b * ABUF;
        const uint32_t aLo = smb + OFF_ALO + b * ABUF;
        const uint32_t bHi = smb + OFF_BHI + b * ABUF;
        const uint32_t bLo = smb + OFF_BLO + b * ABUF;

        #pragma unroll
        for (int ks = 0; ks < 2; ks++) {
            uint32_t Ah[2][4], Al[2][4], Bh[4][4], Bl[4][4];
            #pragma unroll
            for (int mi = 0; mi < 2; mi++) {
                ldsm_x4(Ah[mi], aHi + aoffs + mi * 16 * LDS_ROW + ks * 32);
                ldsm_x4(Al[mi], aLo + aoffs + mi * 16 * LDS_ROW + ks * 32);
            }
            #pragma unroll
            for (int ni = 0; ni < 4; ni++) {
                ldsm_x4(Bh[ni], bHi + boffs + ni * 16 * LDS_ROW + ks * 32);
                ldsm_x4(Bl[ni], bLo + boffs + ni * 16 * LDS_ROW + ks * 32);
            }
            #pragma unroll
            for (int mi = 0; mi < 2; mi++) {
                #pragma unroll
                for (int nj = 0; nj < 8; nj++) {
                    const int ni = nj >> 1, h = (nj & 1) * 2;
                    mma16816(acc[mi][nj], Ah[mi], Bh[ni][h], Bh[ni][h + 1]);
                    mma16816(acc[mi][nj], Ah[mi], Bl[ni][h], Bl[ni][h + 1]);
                    mma16816(acc[mi][nj], Al[mi], Bh[ni][h], Bh[ni][h + 1]);
                }
            }
        }
        __syncthreads();
    }

    // Epilogue
    const int g = lane >> 2, tig = lane & 3;
    const float* bias = args.bias;
    const float* resid = args.resid;
    #pragma unroll
    for (int mi = 0; mi < 2; mi++) {
        #pragma unroll
        for (int nj = 0; nj < 8; nj++) {
            const int r0 = rowBase + m0 + mi * 16 + g;
            const int col = colBase + n0 + nj * 8 + tig * 2;
            float2 v0 = make_float2(acc[mi][nj][0], acc[mi][nj][1]);
            float2 v1 = make_float2(acc[mi][nj][2], acc[mi][nj][3]);
            if (bias) {
                const float2 bi = *(const float2*)(bias + col);
                v0.x += bi.x; v0.y += bi.y;
                v1.x += bi.x; v1.y += bi.y;
                if (r0 < Mvalid) {
                    const float2 rr = *(const float2*)(resid + (long)r0 * ldc + col);
                    v0.x += rr.x; v0.y += rr.y;
                }
                if (r0 + 8 < Mvalid) {
                    const float2 rr = *(const float2*)(resid + (long)(r0 + 8) * ldc + col);
                    v1.x += rr.x; v1.y += rr.y;
                }
            }
            if (r0 < Mvalid)     *(float2*)(C + (long)r0 * ldc + col)       = v0;
            if (r0 + 8 < Mvalid) *(float2*)(C + (long)(r0 + 8) * ldc + col) = v1;
        }
    }
}

// ============================================================================
// Attention: per-thread q-row, K/V (77 text + 4 ip keys) in smem.
// ============================================================================
__global__ __launch_bounds__(128)
void attn_kernel(const float* __restrict__ q, const float* __restrict__ kv,
                 float* __restrict__ hs)
{
    __shared__ float ks[TXT][HEAD_DIM];
    __shared__ float vs[TXT][HEAD_DIM];
    __shared__ float ipks[NTOK][HEAD_DIM];
    __shared__ float ipvs[NTOK][HEAD_DIM];

    const int b   = blockIdx.z;
    const int h   = blockIdx.y;
    const int row = blockIdx.x * blockDim.x + threadIdx.x;

    const long slab = (long)NB * TXT * HIDDEN;
    const float* k   = kv;
    const float* v   = kv + slab;
    const float* ipk = kv + 2 * slab;
    const float* ipv = kv + 3 * slab;

    for (int i = threadIdx.x; i < TXT * (HEAD_DIM / 4); i += blockDim.x) {
        int r = i >> 4, c4 = (i & 15) * 4;
        long off = ((long)b * TXT + r) * HIDDEN + h * HEAD_DIM + c4;
        *(float4*)&ks[r][c4] = *(const float4*)(k + off);
        *(float4*)&vs[r][c4] = *(const float4*)(v + off);
    }
    for (int i = threadIdx.x; i < NTOK * (HEAD_DIM / 4); i += blockDim.x) {
        int r = i >> 4, c4 = (i & 15) * 4;
        long off = ((long)b * TXT + r) * HIDDEN + h * HEAD_DIM + c4;
        *(float4*)&ipks[r][c4] = *(const float4*)(ipk + off);
        *(float4*)&ipvs[r][c4] = *(const float4*)(ipv + off);
    }
    __syncthreads();

    float qr[HEAD_DIM];
    {
        const float* qp = q + ((long)b * SQ + row) * HIDDEN + h * HEAD_DIM;
        #pragma unroll
        for (int i = 0; i < 16; i++) {
            float4 t = *(const float4*)(qp + i * 4);
            qr[4 * i + 0] = t.x; qr[4 * i + 1] = t.y;
            qr[4 * i + 2] = t.z; qr[4 * i + 3] = t.w;
        }
    }

    const float scale = 0.125f;

    float m = -1e30f;
    for (int key = 0; key < TXT; key++) {
        const float4* kk4 = (const float4*)ks[key];
        float s = 0.f;
        #pragma unroll
        for (int i = 0; i < 16; i++) {
            float4 t = kk4[i];
            s = fmaf(qr[4*i+0], t.x, s);
            s = fmaf(qr[4*i+1], t.y, s);
            s = fmaf(qr[4*i+2], t.z, s);
            s = fmaf(qr[4*i+3], t.w, s);
        }
        m = fmaxf(m, s * scale);
    }

    float acc[HEAD_DIM];
    #pragma unroll
    for (int d = 0; d < HEAD_DIM; d++) acc[d] = 0.f;
    float l = 0.f;
    for (int key = 0; key < TXT; key++) {
        const float4* kk4 = (const float4*)ks[key];
        float s = 0.f;
        #pragma unroll
        for (int i = 0; i < 16; i++) {
            float4 t = kk4[i];
            s = fmaf(qr[4*i+0], t.x, s);
            s = fmaf(qr[4*i+1], t.y, s);
            s = fmaf(qr[4*i+2], t.z, s);
            s = fmaf(qr[4*i+3], t.w, s);
        }
        float p = __expf(s * scale - m);
        l += p;
        const float4* vv4 = (const float4*)vs[key];
        #pragma unroll
        for (int i = 0; i < 16; i++) {
            float4 t = vv4[i];
            acc[4*i+0] = fmaf(p, t.x, acc[4*i+0]);
            acc[4*i+1] = fmaf(p, t.y, acc[4*i+1]);
            acc[4*i+2] = fmaf(p, t.z, acc[4*i+2]);
            acc[4*i+3] = fmaf(p, t.w, acc[4*i+3]);
        }
    }
    float inv = 1.f / l;
    #pragma unroll
    for (int d = 0; d < HEAD_DIM; d++) acc[d] *= inv;

    if (b & 1) {
        float smv[NTOK];
        float m2 = -1e30f;
        #pragma unroll
        for (int key = 0; key < NTOK; key++) {
            const float4* kk4 = (const float4*)ipks[key];
            float s = 0.f;
            #pragma unroll
            for (int i = 0; i < 16; i++) {
                float4 t = kk4[i];
                s = fmaf(qr[4*i+0], t.x, s);
                s = fmaf(qr[4*i+1], t.y, s);
                s = fmaf(qr[4*i+2], t.z, s);
                s = fmaf(qr[4*i+3], t.w, s);
            }
            smv[key] = s * scale;
            m2 = fmaxf(m2, smv[key]);
        }
        float l2 = 0.f;
        float p[NTOK];
        #pragma unroll
        for (int key = 0; key < NTOK; key++) { p[key] = __expf(smv[key] - m2); l2 += p[key]; }
        float inv2 = 1.f / l2;
        #pragma unroll
        for (int key = 0; key < NTOK; key++) {
            float pw = p[key] * inv2;
            const float4* vv4 = (const float4*)ipvs[key];
            #pragma unroll
            for (int i = 0; i < 16; i++) {
                float4 t = vv4[i];
                acc[4*i+0] = fmaf(pw, t.x, acc[4*i+0]);
                acc[4*i+1] = fmaf(pw, t.y, acc[4*i+1]);
                acc[4*i+2] = fmaf(pw, t.z, acc[4*i+2]);
                acc[4*i+3] = fmaf(pw, t.w, acc[4*i+3]);
            }
        }
    }

    float* op = hs + ((long)b * SQ + row) * HIDDEN + h * HEAD_DIM;
    #pragma unroll
    for (int i = 0; i < 16; i++)
        *(float4*)(op + i * 4) = make_float4(acc[4*i+0], acc[4*i+1], acc[4*i+2], acc[4*i+3]);
}

// ============================================================================
// Launcher
// ============================================================================
extern "C" void kernel_launch(void* const* d_in, const int* in_sizes, int n_in,
                              void* d_out, int out_size)
{
    const float* hidden = (const float*)d_in[0];
    const float* enc    = (const float*)d_in[1];
    const float* Wq     = (const float*)d_in[2];
    const float* Wk     = (const float*)d_in[3];
    const float* Wv     = (const float*)d_in[4];
    const float* Wk_ip  = (const float*)d_in[5];
    const float* Wv_ip  = (const float*)d_in[6];
    const float* Wout   = (const float*)d_in[7];
    const float* b_out  = (const float*)d_in[8];
    float* out = (float*)d_out;

    static bool attr_set = false;
    if (!attr_set) {
        cudaFuncSetAttribute(hmma_gemm, cudaFuncAttributeMaxDynamicSharedMemorySize, SMEM_TOT);
        attr_set = true;
    }

    __nv_bfloat16 *ahi, *alo, *ehi, *elo, *wqh, *wql, *wth, *wtl, *woh, *wol;
    float *q, *hs, *kv;
    cudaGetSymbolAddress((void**)&ahi, g_ahi);
    cudaGetSymbolAddress((void**)&alo, g_alo);
    cudaGetSymbolAddress((void**)&ehi, g_ehi);
    cudaGetSymbolAddress((void**)&elo, g_elo);
    cudaGetSymbolAddress((void**)&wqh, g_wqT_hi);
    cudaGetSymbolAddress((void**)&wql, g_wqT_lo);
    cudaGetSymbolAddress((void**)&wth, g_wT_hi);
    cudaGetSymbolAddress((void**)&wtl, g_wT_lo);
    cudaGetSymbolAddress((void**)&woh, g_woutT_hi);
    cudaGetSymbolAddress((void**)&wol, g_woutT_lo);
    cudaGetSymbolAddress((void**)&q,   g_q);
    cudaGetSymbolAddress((void**)&hs,  g_hs);
    cudaGetSymbolAddress((void**)&kv,  g_kv);

    const int M_big = NB * SQ;  // 16384
    const long WSLAB = (long)HIDDEN * CROSS;

    // 1) activation splits
    {
        int n4 = M_big * HIDDEN / 4;
        split_kernel<<<(n4 + 255) / 256, 256>>>(hidden, ahi, alo, n4);
    }
    {
        int n4 = NB * ENC * CROSS / 4;
        split_kernel<<<(n4 + 255) / 256, 256>>>(enc, ehi, elo, n4);
    }

    // 2) weight transposes + splits
    dim3 tb(32, 8);
    transpose_split_kernel<<<dim3(HIDDEN / 32, HIDDEN / 32), tb>>>(Wq, HIDDEN, HIDDEN, wqh, wql);
    transpose_split_kernel<<<dim3(HIDDEN / 32, CROSS / 32), tb>>>(Wk,    CROSS, HIDDEN, wth + 0 * WSLAB, wtl + 0 * WSLAB);
    transpose_split_kernel<<<dim3(HIDDEN / 32, CROSS / 32), tb>>>(Wv,    CROSS, HIDDEN, wth + 1 * WSLAB, wtl + 1 * WSLAB);
    transpose_split_kernel<<<dim3(HIDDEN / 32, CROSS / 32), tb>>>(Wk_ip, CROSS, HIDDEN, wth + 2 * WSLAB, wtl + 2 * WSLAB);
    transpose_split_kernel<<<dim3(HIDDEN / 32, CROSS / 32), tb>>>(Wv_ip, CROSS, HIDDEN, wth + 3 * WSLAB, wtl + 3 * WSLAB);
    transpose_split_kernel<<<dim3(HIDDEN / 32, HIDDEN / 32), tb>>>(Wout, HIDDEN, HIDDEN, woh, wol);

    // 3) Q = hidden @ Wq
    {
        GemmArgs a = {ahi, alo, wqh, wql, q, 0, 0, M_big, HIDDEN, HIDDEN,
                      nullptr, nullptr, 0};
        hmma_gemm<<<dim3(HIDDEN / 128, M_big / 128, 1), 256, SMEM_TOT>>>(a);
    }

    // 4) merged K/V/ipK/ipV projections (grid.z = 16)
    {
        GemmArgs a = {ehi, elo, wth, wtl, kv, 0, 0, TXT, CROSS, HIDDEN,
                      nullptr, nullptr, 1};
        hmma_gemm<<<dim3(HIDDEN / 128, 1, 16), 256, SMEM_TOT>>>(a);
    }

    // 5) attention
    attn_kernel<<<dim3(SQ / 128, NHEADS, NB), 128>>>(q, kv, hs);

    // 6) split hs (reuse ahi/alo)
    {
        int n4 = M_big * HIDDEN / 4;
        split_kernel<<<(n4 + 255) / 256, 256>>>(hs, ahi, alo, n4);
    }

    // 7) out = hs @ Wout + b_out + residual
    {
        GemmArgs a = {ahi, alo, woh, wol, out, 0, 0, M_big, HIDDEN, HIDDEN,
                      b_out, hidden, 0};
        hmma_gemm<<<dim3(HIDDEN / 128, M_big / 128, 1), 256, SMEM_TOT>>>(a);
    }
}

// round 4
// speedup vs baseline: 2.8655x; 1.0926x over previous
#include <cuda_runtime.h>
#include <cuda_bf16.h>
#include <cstdint>

#define NHEADS 20
#define HEAD_DIM 64
#define HIDDEN 1280
#define CROSS 2048
#define NB 4
#define SQ 4096
#define TXT 77
#define NTOK 4
#define ENC (TXT + NTOK)

// ============================================================================
// PTX helpers (baseline-family only: mma.sync / ldmatrix / cp.async)
// ============================================================================
__device__ __forceinline__ uint32_t smem_to_u32(const void* smem_ptr) {
    uint32_t addr;
    asm("{ .reg .u64 tmp; cvta.to.shared.u64 tmp, %1; cvt.u32.u64 %0, tmp; }"
        : "=r"(addr) : "l"(smem_ptr));
    return addr;
}

__device__ __forceinline__ void cp_async16(uint32_t dst, const void* src, int bytes) {
    asm volatile("cp.async.cg.shared.global [%0], [%1], 16, %2;"
                 :: "r"(dst), "l"(src), "r"(bytes));
}
#define CP_COMMIT() asm volatile("cp.async.commit_group;" ::: "memory")
#define CP_WAIT(N)  asm volatile("cp.async.wait_group %0;" :: "n"(N) : "memory")

__device__ __forceinline__ void ldsm_x4(uint32_t* r, uint32_t a) {
    asm volatile("ldmatrix.sync.aligned.m8n8.x4.shared.b16 {%0,%1,%2,%3}, [%4];"
                 : "=r"(r[0]), "=r"(r[1]), "=r"(r[2]), "=r"(r[3]) : "r"(a));
}

__device__ __forceinline__ void mma16816(float* c, const uint32_t* a,
                                         uint32_t b0, uint32_t b1) {
    asm volatile(
        "mma.sync.aligned.m16n8k16.row.col.f32.bf16.bf16.f32 "
        "{%0,%1,%2,%3},{%4,%5,%6,%7},{%8,%9},{%0,%1,%2,%3};"
        : "+f"(c[0]), "+f"(c[1]), "+f"(c[2]), "+f"(c[3])
        : "r"(a[0]), "r"(a[1]), "r"(a[2]), "r"(a[3]), "r"(b0), "r"(b1));
}

// ============================================================================
// Scratch (static device allocations)
// ============================================================================
__device__ __nv_bfloat16 g_ahi[NB * SQ * HIDDEN];
__device__ __nv_bfloat16 g_alo[NB * SQ * HIDDEN];
__device__ __nv_bfloat16 g_ehi[NB * ENC * CROSS];
__device__ __nv_bfloat16 g_elo[NB * ENC * CROSS];
__device__ __nv_bfloat16 g_wqT_hi[HIDDEN * HIDDEN];
__device__ __nv_bfloat16 g_wqT_lo[HIDDEN * HIDDEN];
__device__ __nv_bfloat16 g_wT_hi[4 * HIDDEN * CROSS];   // wk, wv, wkip, wvip (transposed)
__device__ __nv_bfloat16 g_wT_lo[4 * HIDDEN * CROSS];
__device__ __nv_bfloat16 g_woutT_hi[HIDDEN * HIDDEN];
__device__ __nv_bfloat16 g_woutT_lo[HIDDEN * HIDDEN];
__device__ float g_q[NB * SQ * HIDDEN];
__device__ float g_kv[4 * NB * TXT * HIDDEN];           // k, v, ipk, ipv (uniform stride)

// ============================================================================
// fp32 -> bf16 hi/lo split (float4 vectorized)
// ============================================================================
__global__ __launch_bounds__(256)
void split_kernel(const float* __restrict__ in, __nv_bfloat16* __restrict__ hi,
                  __nv_bfloat16* __restrict__ lo, int n4)
{
    int i = blockIdx.x * blockDim.x + threadIdx.x;
    if (i >= n4) return;
    float4 x = ((const float4*)in)[i];
    __nv_bfloat16 h0 = __float2bfloat16(x.x);
    __nv_bfloat16 h1 = __float2bfloat16(x.y);
    __nv_bfloat16 h2 = __float2bfloat16(x.z);
    __nv_bfloat16 h3 = __float2bfloat16(x.w);
    __nv_bfloat162 hA; hA.x = h0; hA.y = h1;
    __nv_bfloat162 hB; hB.x = h2; hB.y = h3;
    ((__nv_bfloat162*)hi)[2 * i]     = hA;
    ((__nv_bfloat162*)hi)[2 * i + 1] = hB;
    __nv_bfloat162 lA;
    lA.x = __float2bfloat16(x.x - __bfloat162float(h0));
    lA.y = __float2bfloat16(x.y - __bfloat162float(h1));
    __nv_bfloat162 lB;
    lB.x = __float2bfloat16(x.z - __bfloat162float(h2));
    lB.y = __float2bfloat16(x.w - __bfloat162float(h3));
    ((__nv_bfloat162*)lo)[2 * i]     = lA;
    ((__nv_bfloat162*)lo)[2 * i + 1] = lB;
}

// ============================================================================
// Merged transpose + split of all 6 weights (grid.z selects weight).
// in[K][1280] fp32 -> out_hi/out_lo [1280][K] bf16. N fixed = HIDDEN.
// Grid: (1280/32, 2048/32, 6); blocks with k0 >= K[w] exit early.
// ============================================================================
struct TSArgs {
    const float* src[6];
    __nv_bfloat16* dhi[6];
    __nv_bfloat16* dlo[6];
    int K[6];
};

__global__ __launch_bounds__(256)
void transpose_split_all(TSArgs args)
{
    const int w = blockIdx.z;
    const int K = args.K[w];
    const int k0 = blockIdx.y * 32;
    if (k0 >= K) return;
    const float* in = args.src[w];
    __nv_bfloat16* ohi = args.dhi[w];
    __nv_bfloat16* olo = args.dlo[w];

    __shared__ float t[32][33];
    const int tx = threadIdx.x, ty = threadIdx.y;
    const int n0 = blockIdx.x * 32;
    #pragma unroll
    for (int j = ty; j < 32; j += 8)
        t[j][tx] = in[(long)(k0 + j) * HIDDEN + n0 + tx];
    __syncthreads();
    #pragma unroll
    for (int j = ty; j < 32; j += 8) {
        float x = t[tx][j];
        __nv_bfloat16 h = __float2bfloat16(x);
        long o = (long)(n0 + j) * K + k0 + tx;
        ohi[o] = h;
        olo[o] = __float2bfloat16(x - __bfloat162float(h));
    }
}

// ============================================================================
// HMMA GEMM: C[M,N] = (Ahi+Alo)[M,K] @ (Bhi+Blo)^T  (B stored [N][K] bf16)
// CTA tile 128x128x32, 8 warps (warp tile 32x64), cp.async double buffer.
// 3-term bf16 split. Optional fused bias+residual. 2 CTAs/SM target.
// ============================================================================
#define LDS_ROW 80
#define ABUF    10240
#define OFF_AHI 0
#define OFF_ALO 20480
#define OFF_BHI 40960
#define OFF_BLO 61440
#define SMEM_TOT 81920

struct GemmArgs {
    const __nv_bfloat16 *Ahi, *Alo, *Bhi, *Blo;
    float* C;
    long aBatch, cBatch;
    int Mvalid, K, ldc;
    const float *bias, *resid;
    int kvmode;
};

__device__ __forceinline__ void gemm_load_stage(
    uint32_t smb, int s, int tid, int rowBase, int colBase, int Mvalid, int K,
    const __nv_bfloat16* __restrict__ Ahi, const __nv_bfloat16* __restrict__ Alo,
    const __nv_bfloat16* __restrict__ Bhi, const __nv_bfloat16* __restrict__ Blo)
{
    const int b = s & 1;
    const long k0 = (long)s << 5;
    #pragma unroll
    for (int i = 0; i < 2; i++) {
        int idx = tid + i * 256;
        int r = idx >> 2, c = idx & 3;
        uint32_t d = smb + (uint32_t)(b * ABUF + r * LDS_ROW + c * 16);
        long go = ((long)(rowBase + r)) * K + k0 + c * 8;
        int bytes = (rowBase + r < Mvalid) ? 16 : 0;
        cp_async16(d + OFF_AHI, Ahi + go, bytes);
        cp_async16(d + OFF_ALO, Alo + go, bytes);
        long gb = ((long)(colBase + r)) * K + k0 + c * 8;
        cp_async16(d + OFF_BHI, Bhi + gb, 16);
        cp_async16(d + OFF_BLO, Blo + gb, 16);
    }
    CP_COMMIT();
}

__global__ __launch_bounds__(256, 2)
void hmma_gemm(GemmArgs args)
{
    extern __shared__ __align__(16) char smx[];
    const uint32_t smb = smem_to_u32(smx);
    const int tid = threadIdx.x;

    const __nv_bfloat16* Ahi = args.Ahi;
    const __nv_bfloat16* Alo = args.Alo;
    const __nv_bfloat16* Bhi = args.Bhi;
    const __nv_bfloat16* Blo = args.Blo;
    float* C = args.C;
    int Mvalid = args.Mvalid;
    const int K = args.K, ldc = args.ldc;

    if (args.kvmode) {
        const int gemm = blockIdx.z >> 2;
        const int batch = blockIdx.z & 3;
        const long aoff = (long)batch * ENC * CROSS + (gemm >= 2 ? (long)TXT * CROSS : 0);
        Ahi += aoff;  Alo += aoff;
        Bhi += (long)gemm * HIDDEN * CROSS;
        Blo += (long)gemm * HIDDEN * CROSS;
        C   += ((long)gemm * NB + batch) * TXT * HIDDEN;
        Mvalid = (gemm < 2) ? TXT : NTOK;
    } else {
        Ahi += blockIdx.z * args.aBatch;
        Alo += blockIdx.z * args.aBatch;
        C   += blockIdx.z * args.cBatch;
    }

    const int rowBase = blockIdx.y * 128;
    const int colBase = blockIdx.x * 128;
    const int NS = K >> 5;

    const int warp = tid >> 5, lane = tid & 31;
    const int wm = warp >> 1, wn = warp & 1;
    const int m0 = wm * 32, n0 = wn * 64;

    const uint32_t aoffs = (uint32_t)((m0 + (lane & 15)) * LDS_ROW + (lane >> 4) * 16);
    const uint32_t boffs = (uint32_t)((n0 + ((lane >> 4) & 1) * 8 + (lane & 7)) * LDS_ROW
                                      + ((lane >> 3) & 1) * 16);

    float acc[2][8][4];
    #pragma unroll
    for (int mi = 0; mi < 2; mi++)
        #pragma unroll
        for (int nj = 0; nj < 8; nj++)
            #pragma unroll
            for (int t = 0; t < 4; t++) acc[mi][nj][t] = 0.f;

    gemm_load_stage(smb, 0, tid, rowBase, colBase, Mvalid, K, Ahi, Alo, Bhi, Blo);

    for (int s = 0; s < NS; ++s) {
        if (s + 1 < NS) {
            gemm_load_stage(smb, s + 1, tid, rowBase, colBase, Mvalid, K, Ahi, Alo, Bhi, Blo);
            CP_WAIT(1);
        } else {
            CP_WAIT(0);
        }
        __syncthreads();

        const int b = s & 1;
        const uint32_t aHi = smb + OFF_AHI + b * ABUF;
        const uint32_t aLo = smb + OFF_ALO + b * ABUF;
        const uint32_t bHi = smb + OFF_BHI + b * ABUF;
        const uint32_t bLo = smb + OFF_BLO + b * ABUF;

        #pragma unroll
        for (int ks = 0; ks < 2; ks++) {
            uint32_t Ah[2][4], Al[2][4];
            #pragma unroll
            for (int mi = 0; mi < 2; mi++) {
                ldsm_x4(Ah[mi], aHi + aoffs + mi * 16 * LDS_ROW + ks * 32);
                ldsm_x4(Al[mi], aLo + aoffs + mi * 16 * LDS_ROW + ks * 32);
            }
            // B fragments per 64-col half to cap live registers (2 CTA/SM)
            #pragma unroll
            for (int half = 0; half < 2; half++) {
                uint32_t Bh[2][4], Bl[2][4];
                #pragma unroll
                for (int nn = 0; nn < 2; nn++) {
                    const uint32_t bo = boffs + (half * 2 + nn) * 16 * LDS_ROW + ks * 32;
                    ldsm_x4(Bh[nn], bHi + bo);
                    ldsm_x4(Bl[nn], bLo + bo);
                }
                #pragma unroll
                for (int mi = 0; mi < 2; mi++) {
                    #pragma unroll
                    for (int j4 = 0; j4 < 4; j4++) {
                        const int ni = j4 >> 1, h = (j4 & 1) * 2;
                        float* a = acc[mi][half * 4 + j4];
                        mma16816(a, Ah[mi], Bh[ni][h], Bh[ni][h + 1]);
                        mma16816(a, Ah[mi], Bl[ni][h], Bl[ni][h + 1]);
                        mma16816(a, Al[mi], Bh[ni][h], Bh[ni][h + 1]);
                    }
                }
            }
        }
        __syncthreads();
    }

    // Epilogue
    const int g = lane >> 2, tig = lane & 3;
    const float* bias = args.bias;
    const float* resid = args.resid;
    #pragma unroll
    for (int mi = 0; mi < 2; mi++) {
        #pragma unroll
        for (int nj = 0; nj < 8; nj++) {
            const int r0 = rowBase + m0 + mi * 16 + g;
            const int col = colBase + n0 + nj * 8 + tig * 2;
            float2 v0 = make_float2(acc[mi][nj][0], acc[mi][nj][1]);
            float2 v1 = make_float2(acc[mi][nj][2], acc[mi][nj][3]);
            if (bias) {
                const float2 bi = *(const float2*)(bias + col);
                v0.x += bi.x; v0.y += bi.y;
                v1.x += bi.x; v1.y += bi.y;
                if (r0 < Mvalid) {
                    const float2 rr = *(const float2*)(resid + (long)r0 * ldc + col);
                    v0.x += rr.x; v0.y += rr.y;
                }
                if (r0 + 8 < Mvalid) {
                    const float2 rr = *(const float2*)(resid + (long)(r0 + 8) * ldc + col);
                    v1.x += rr.x; v1.y += rr.y;
                }
            }
            if (r0 < Mvalid)     *(float2*)(C + (long)r0 * ldc + col)       = v0;
            if (r0 + 8 < Mvalid) *(float2*)(C + (long)(r0 + 8) * ldc + col) = v1;
        }
    }
}

// ============================================================================
// Attention: online softmax single-pass, per-thread q-row, K/V in smem.
// Writes bf16 hi/lo split output directly (fused split for out-projection).
// ============================================================================
__global__ __launch_bounds__(128)
void attn_kernel(const float* __restrict__ q, const float* __restrict__ kv,
                 __nv_bfloat16* __restrict__ ohi, __nv_bfloat16* __restrict__ olo)
{
    __shared__ float ks[TXT][HEAD_DIM];
    __shared__ float vs[TXT][HEAD_DIM];
    __shared__ float ipks[NTOK][HEAD_DIM];
    __shared__ float ipvs[NTOK][HEAD_DIM];

    const int b   = blockIdx.z;
    const int h   = blockIdx.y;
    const int row = blockIdx.x * blockDim.x + threadIdx.x;

    const long slab = (long)NB * TXT * HIDDEN;
    const float* k   = kv;
    const float* v   = kv + slab;
    const float* ipk = kv + 2 * slab;
    const float* ipv = kv + 3 * slab;

    for (int i = threadIdx.x; i < TXT * (HEAD_DIM / 4); i += blockDim.x) {
        int r = i >> 4, c4 = (i & 15) * 4;
        long off = ((long)b * TXT + r) * HIDDEN + h * HEAD_DIM + c4;
        *(float4*)&ks[r][c4] = *(const float4*)(k + off);
        *(float4*)&vs[r][c4] = *(const float4*)(v + off);
    }
    for (int i = threadIdx.x; i < NTOK * (HEAD_DIM / 4); i += blockDim.x) {
        int r = i >> 4, c4 = (i & 15) * 4;
        long off = ((long)b * TXT + r) * HIDDEN + h * HEAD_DIM + c4;
        *(float4*)&ipks[r][c4] = *(const float4*)(ipk + off);
        *(float4*)&ipvs[r][c4] = *(const float4*)(ipv + off);
    }
    __syncthreads();

    float qr[HEAD_DIM];
    {
        const float* qp = q + ((long)b * SQ + row) * HIDDEN + h * HEAD_DIM;
        #pragma unroll
        for (int i = 0; i < 16; i++) {
            float4 t = *(const float4*)(qp + i * 4);
            qr[4 * i + 0] = t.x; qr[4 * i + 1] = t.y;
            qr[4 * i + 2] = t.z; qr[4 * i + 3] = t.w;
        }
    }

    const float scale = 0.125f;

    // online softmax, single pass over text keys
    float acc[HEAD_DIM];
    #pragma unroll
    for (int d = 0; d < HEAD_DIM; d++) acc[d] = 0.f;
    float m = -1e30f, l = 0.f;

    for (int key = 0; key < TXT; key++) {
        const float4* kk4 = (const float4*)ks[key];
        float s = 0.f;
        #pragma unroll
        for (int i = 0; i < 16; i++) {
            float4 t = kk4[i];
            s = fmaf(qr[4*i+0], t.x, s);
            s = fmaf(qr[4*i+1], t.y, s);
            s = fmaf(qr[4*i+2], t.z, s);
            s = fmaf(qr[4*i+3], t.w, s);
        }
        s *= scale;
        if (s > m) {
            float corr = __expf(m - s);
            l *= corr;
            #pragma unroll
            for (int d = 0; d < HEAD_DIM; d++) acc[d] *= corr;
            m = s;
        }
        float p = __expf(s - m);
        l += p;
        const float4* vv4 = (const float4*)vs[key];
        #pragma unroll
        for (int i = 0; i < 16; i++) {
            float4 t = vv4[i];
            acc[4*i+0] = fmaf(p, t.x, acc[4*i+0]);
            acc[4*i+1] = fmaf(p, t.y, acc[4*i+1]);
            acc[4*i+2] = fmaf(p, t.z, acc[4*i+2]);
            acc[4*i+3] = fmaf(p, t.w, acc[4*i+3]);
        }
    }
    float inv = 1.f / l;
    #pragma unroll
    for (int d = 0; d < HEAD_DIM; d++) acc[d] *= inv;

    // ip attention (separate softmax over 4 keys), only odd batches
    if (b & 1) {
        float smv[NTOK];
        float m2 = -1e30f;
        #pragma unroll
        for (int key = 0; key < NTOK; key++) {
            const float4* kk4 = (const float4*)ipks[key];
            float s = 0.f;
            #pragma unroll
            for (int i = 0; i < 16; i++) {
                float4 t = kk4[i];
                s = fmaf(qr[4*i+0], t.x, s);
                s = fmaf(qr[4*i+1], t.y, s);
                s = fmaf(qr[4*i+2], t.z, s);
                s = fmaf(qr[4*i+3], t.w, s);
            }
            smv[key] = s * scale;
            m2 = fmaxf(m2, smv[key]);
        }
        float l2 = 0.f;
        float p[NTOK];
        #pragma unroll
        for (int key = 0; key < NTOK; key++) { p[key] = __expf(smv[key] - m2); l2 += p[key]; }
        float inv2 = 1.f / l2;
        #pragma unroll
        for (int key = 0; key < NTOK; key++) {
            float pw = p[key] * inv2;
            const float4* vv4 = (const float4*)ipvs[key];
            #pragma unroll
            for (int i = 0; i < 16; i++) {
                float4 t = vv4[i];
                acc[4*i+0] = fmaf(pw, t.x, acc[4*i+0]);
                acc[4*i+1] = fmaf(pw, t.y, acc[4*i+1]);
                acc[4*i+2] = fmaf(pw, t.z, acc[4*i+2]);
                acc[4*i+3] = fmaf(pw, t.w, acc[4*i+3]);
            }
        }
    }

    // fused bf16 hi/lo split output
    const long ob = ((long)b * SQ + row) * HIDDEN + h * HEAD_DIM;
    __nv_bfloat16* hp = ohi + ob;
    __nv_bfloat16* lp = olo + ob;
    #pragma unroll
    for (int i = 0; i < 64; i += 8) {
        uint32_t ph[2], pl[2];
        #pragma unroll
        for (int j = 0; j < 2; j++) {
            __nv_bfloat162 th, tl;
            float a0 = acc[i + j * 2], a1 = acc[i + j * 2 + 1];
            th.x = __float2bfloat16(a0);
            th.y = __float2bfloat16(a1);
            tl.x = __float2bfloat16(a0 - __bfloat162float(th.x));
            tl.y = __float2bfloat16(a1 - __bfloat162float(th.y));
            ph[j] = *reinterpret_cast<uint32_t*>(&th);
            pl[j] = *reinterpret_cast<uint32_t*>(&tl);
        }
        uint32_t ph2[2], pl2[2];
        #pragma unroll
        for (int j = 0; j < 2; j++) {
            __nv_bfloat162 th, tl;
            float a0 = acc[i + 4 + j * 2], a1 = acc[i + 4 + j * 2 + 1];
            th.x = __float2bfloat16(a0);
            th.y = __float2bfloat16(a1);
            tl.x = __float2bfloat16(a0 - __bfloat162float(th.x));
            tl.y = __float2bfloat16(a1 - __bfloat162float(th.y));
            ph2[j] = *reinterpret_cast<uint32_t*>(&th);
            pl2[j] = *reinterpret_cast<uint32_t*>(&tl);
        }
        *(uint4*)(hp + i) = make_uint4(ph[0], ph[1], ph2[0], ph2[1]);
        *(uint4*)(lp + i) = make_uint4(pl[0], pl[1], pl2[0], pl2[1]);
    }
}

// ============================================================================
// Launcher
// ============================================================================
extern "C" void kernel_launch(void* const* d_in, const int* in_sizes, int n_in,
                              void* d_out, int out_size)
{
    const float* hidden = (const float*)d_in[0];
    const float* enc    = (const float*)d_in[1];
    const float* Wq     = (const float*)d_in[2];
    const float* Wk     = (const float*)d_in[3];
    const float* Wv     = (const float*)d_in[4];
    const float* Wk_ip  = (const float*)d_in[5];
    const float* Wv_ip  = (const float*)d_in[6];
    const float* Wout   = (const float*)d_in[7];
    const float* b_out  = (const float*)d_in[8];
    float* out = (float*)d_out;

    static bool attr_set = false;
    if (!attr_set) {
        cudaFuncSetAttribute(hmma_gemm, cudaFuncAttributeMaxDynamicSharedMemorySize, SMEM_TOT);
        attr_set = true;
    }

    __nv_bfloat16 *ahi, *alo, *ehi, *elo, *wqh, *wql, *wth, *wtl, *woh, *wol;
    float *q, *kv;
    cudaGetSymbolAddress((void**)&ahi, g_ahi);
    cudaGetSymbolAddress((void**)&alo, g_alo);
    cudaGetSymbolAddress((void**)&ehi, g_ehi);
    cudaGetSymbolAddress((void**)&elo, g_elo);
    cudaGetSymbolAddress((void**)&wqh, g_wqT_hi);
    cudaGetSymbolAddress((void**)&wql, g_wqT_lo);
    cudaGetSymbolAddress((void**)&wth, g_wT_hi);
    cudaGetSymbolAddress((void**)&wtl, g_wT_lo);
    cudaGetSymbolAddress((void**)&woh, g_woutT_hi);
    cudaGetSymbolAddress((void**)&wol, g_woutT_lo);
    cudaGetSymbolAddress((void**)&q,   g_q);
    cudaGetSymbolAddress((void**)&kv,  g_kv);

    const int M_big = NB * SQ;  // 16384
    const long WSLAB = (long)HIDDEN * CROSS;

    // 1) activation splits
    {
        int n4 = M_big * HIDDEN / 4;
        split_kernel<<<(n4 + 255) / 256, 256>>>(hidden, ahi, alo, n4);
    }
    {
        int n4 = NB * ENC * CROSS / 4;
        split_kernel<<<(n4 + 255) / 256, 256>>>(enc, ehi, elo, n4);
    }

    // 2) all weight transposes+splits in one launch
    {
        TSArgs t;
        t.src[0] = Wq;    t.dhi[0] = wqh;             t.dlo[0] = wql;             t.K[0] = HIDDEN;
        t.src[1] = Wk;    t.dhi[1] = wth + 0 * WSLAB; t.dlo[1] = wtl + 0 * WSLAB; t.K[1] = CROSS;
        t.src[2] = Wv;    t.dhi[2] = wth + 1 * WSLAB; t.dlo[2] = wtl + 1 * WSLAB; t.K[2] = CROSS;
        t.src[3] = Wk_ip; t.dhi[3] = wth + 2 * WSLAB; t.dlo[3] = wtl + 2 * WSLAB; t.K[3] = CROSS;
        t.src[4] = Wv_ip; t.dhi[4] = wth + 3 * WSLAB; t.dlo[4] = wtl + 3 * WSLAB; t.K[4] = CROSS;
        t.src[5] = Wout;  t.dhi[5] = woh;             t.dlo[5] = wol;             t.K[5] = HIDDEN;
        transpose_split_all<<<dim3(HIDDEN / 32, CROSS / 32, 6), dim3(32, 8)>>>(t);
    }

    // 3) Q = hidden @ Wq
    {
        GemmArgs a = {ahi, alo, wqh, wql, q, 0, 0, M_big, HIDDEN, HIDDEN,
                      nullptr, nullptr, 0};
        hmma_gemm<<<dim3(HIDDEN / 128, M_big / 128, 1), 256, SMEM_TOT>>>(a);
    }

    // 4) merged K/V/ipK/ipV projections (grid.z = 16)
    {
        GemmArgs a = {ehi, elo, wth, wtl, kv, 0, 0, TXT, CROSS, HIDDEN,
                      nullptr, nullptr, 1};
        hmma_gemm<<<dim3(HIDDEN / 128, 1, 16), 256, SMEM_TOT>>>(a);
    }

    // 5) attention -> bf16 hi/lo (reuses ahi/alo; hidden split consumed by Q GEMM)
    attn_kernel<<<dim3(SQ / 128, NHEADS, NB), 128>>>(q, kv, ahi, alo);

    // 6) out = hs @ Wout + b_out + residual
    {
        GemmArgs a = {ahi, alo, woh, wol, out, 0, 0, M_big, HIDDEN, HIDDEN,
                      b_out, hidden, 0};
        hmma_gemm<<<dim3(HIDDEN / 128, M_big / 128, 1), 256, SMEM_TOT>>>(a);
    }
}